// round 9
// baseline (speedup 1.0000x reference)
#include <cuda_runtime.h>
#include <cuda_fp16.h>
#include <stdint.h>

#define BB 128
#define TT 1024
#define DD 64
#define HH 256
#define OO 128

// ---------------- global state -------------------------------------------------
__device__ __half g_h1[(TT + 1)][BB][HH];   // full h1 history (L1 -> L2 handoff)
__device__ __half g_h2f[BB][HH];            // final h2(T) only
__device__ int    g_f1[(TT + 1)][8][8];     // per-producer flags for h1
__device__ int    g_abort;

__device__ __forceinline__ uint32_t packh2(float a, float b) {
    __half2 h = __floats2half2_rn(a, b);
    return *reinterpret_cast<uint32_t*>(&h);
}

__device__ __forceinline__ void mma16816(float& c0, float& c1, float& c2, float& c3,
                                         uint32_t a0, uint32_t a1, uint32_t a2, uint32_t a3,
                                         uint32_t b0, uint32_t b1) {
    asm volatile(
        "mma.sync.aligned.m16n8k16.row.col.f32.f16.f16.f32 "
        "{%0,%1,%2,%3}, {%4,%5,%6,%7}, {%8,%9}, {%0,%1,%2,%3};\n"
        : "+f"(c0), "+f"(c1), "+f"(c2), "+f"(c3)
        : "r"(a0), "r"(a1), "r"(a2), "r"(a3), "r"(b0), "r"(b1));
}

__device__ __forceinline__ uint32_t smem_u32(const void* p) {
    uint32_t a;
    asm("{ .reg .u64 t; cvta.to.shared.u64 t, %1; cvt.u32.u64 %0, t; }" : "=r"(a) : "l"(p));
    return a;
}

__device__ __forceinline__ uint32_t mapa32(uint32_t addr, uint32_t rank) {
    uint32_t r;
    asm("mapa.shared::cluster.u32 %0, %1, %2;" : "=r"(r) : "r"(addr), "r"(rank));
    return r;
}

__device__ __forceinline__ void bulk_s2s(uint32_t dst, uint32_t src, uint32_t bytes,
                                         uint32_t rmb) {
    asm volatile(
        "cp.async.bulk.shared::cluster.shared::cta.mbarrier::complete_tx::bytes "
        "[%0], [%1], %2, [%3];"
        :: "r"(dst), "r"(src), "r"(bytes), "r"(rmb) : "memory");
}

__device__ __forceinline__ void mb_init(uint32_t mb, uint32_t cnt) {
    asm volatile("mbarrier.init.shared.b64 [%0], %1;" :: "r"(mb), "r"(cnt) : "memory");
}

__device__ __forceinline__ void mb_arrive_expect(uint32_t mb, uint32_t bytes) {
    asm volatile("mbarrier.arrive.expect_tx.shared.b64 _, [%0], %1;"
                 :: "r"(mb), "r"(bytes) : "memory");
}

// cta-scope acquire (cluster-scope acquire suspected to lower to ~490cyc UCGABAR)
__device__ __forceinline__ void mb_wait(uint32_t mb, uint32_t ph) {
    uint32_t done = 0, n = 0;
    while (!done) {
        asm volatile(
            "{\n\t.reg .pred p;\n\t"
            "mbarrier.try_wait.parity.acquire.cta.shared::cta.b64 p, [%1], %2, 0x989680;\n\t"
            "selp.b32 %0, 1, 0, p;\n\t}"
            : "=r"(done) : "r"(mb), "r"(ph) : "memory");
        if (!done) {
            if (*(volatile int*)&g_abort) break;
            if (++n > (1u << 22)) { *(volatile int*)&g_abort = 1; break; }
        }
    }
}

__device__ __forceinline__ int ld_acq(const int* p) {
    int v;
    asm volatile("ld.acquire.gpu.global.s32 %0, [%1];" : "=r"(v) : "l"(p) : "memory");
    return v;
}

__device__ __forceinline__ void red_rel(int* p) {
    asm volatile("red.release.gpu.global.add.s32 [%0], %1;" :: "l"(p), "r"(1) : "memory");
}

#define BAR_ARRIVE_256(id) asm volatile("bar.arrive " #id ", 256;" ::: "memory")
#define BAR_SYNC_256(id)   asm volatile("bar.sync "   #id ", 256;" ::: "memory")
#define BAR_SYNC_128(id)   asm volatile("bar.sync "   #id ", 128;" ::: "memory")

// ---------------- init (runs LAST: prepares flags for the NEXT launch) ---------
__global__ void k_init() {
    int* p = &g_f1[0][0][0];
    const int n = (TT + 1) * 8 * 8;
    for (int i = blockIdx.x * blockDim.x + threadIdx.x; i < n;
         i += gridDim.x * blockDim.x)
        p[i] = 0;
    if (blockIdx.x == 0 && threadIdx.x == 0) g_abort = 0;
}

// ---------------- persistent RNN: 16 clusters of 8 CTAs, 256 thr/CTA -----------
// warps 0-3: recurrence (phase B + epilogue + broadcast)
// warps 4-7: non-recurrent producer (x/h1 staging + phase A MMA -> fp32 partials)
__global__ void __launch_bounds__(256, 1) __cluster_dims__(8, 1, 1)
k_rnn(const float* __restrict__ x,
      const float* __restrict__ Wx1, const float* __restrict__ Wh1,
      const float* __restrict__ b1,
      const float* __restrict__ Wx2, const float* __restrict__ Wh2,
      const float* __restrict__ b2) {
    const int tid  = threadIdx.x;
    const int lane = tid & 31;
    const int w    = tid >> 5;         // 0..7

    uint32_t rank;
    asm("mov.u32 %0, %%cluster_ctarank;" : "=r"(rank));

    const int  cl   = blockIdx.x >> 3;
    const bool isL2 = (cl >= 8);
    const int  bg   = isL2 ? cl - 8 : cl;

    // shared memory
    // s_buf[buf][producer][row16][col16 b32]: 1KB blocks, also bulk-copy source
    __shared__ __align__(16) uint32_t s_buf[2][8][16][16];   // 16 KB
    __shared__ __align__(16) uint32_t s_stage[16 * 132];     //  8.25 KB
    __shared__ __align__(16) float2   s_pA[2][16][18];       //  4.5 KB
    __shared__ __align__(8)  uint64_t s_mb[4];               // [buf][grpAB]

    const uint32_t buf_a = smem_u32(&s_buf[0][0][0][0]);
    const uint32_t mb_a  = smem_u32(&s_mb[0]);

    for (int i = tid; i < 2 * 8 * 16 * 16; i += 256) (&s_buf[0][0][0][0])[i] = 0;
    if (tid == 0) {
        mb_init(mb_a,      1);  // buf0 grpA
        mb_init(mb_a + 8,  1);  // buf0 grpB
        mb_init(mb_a + 16, 1);  // buf1 grpA
        mb_init(mb_a + 24, 1);  // buf1 grpB
        asm volatile("fence.mbarrier_init.release.cluster;" ::: "memory");
    }
    __syncthreads();
    asm volatile("barrier.cluster.arrive.aligned;" ::: "memory");
    asm volatile("barrier.cluster.wait.aligned;"   ::: "memory");
    if (tid == 0) {  // pre-arm all 4 (grpA: 3 copies, grpB: 4 copies)
        mb_arrive_expect(mb_a,      3072);
        mb_arrive_expect(mb_a + 8,  4096);
        mb_arrive_expect(mb_a + 16, 3072);
        mb_arrive_expect(mb_a + 24, 4096);
    }

    if (w < 4) {
        // ================= B-warps: recurrence =================
        const int grp = lane >> 2;     // 0..7
        const int tg  = lane & 3;      // 0..3
        const int n0  = (int)rank * 32 + w * 8;
        const int ncol = n0 + grp;
        const int sw  = (grp & 6) * 2;

        // weight fragments permuted into ARRIVAL order: j-th group = producer (rank-j)&7
        uint32_t bfB[16][2];
#pragma unroll
        for (int j = 0; j < 8; ++j) {
            const int pj = ((int)rank + 8 - j) & 7;
#pragma unroll
            for (int half = 0; half < 2; ++half) {
                const float* W = isL2 ? Wh2 : Wh1;
                int r0 = (pj * 2 + half) * 16 + tg * 2;
                bfB[j * 2 + half][0] = packh2(W[(r0 + 0) * HH + ncol], W[(r0 + 1) * HH + ncol]);
                bfB[j * 2 + half][1] = packh2(W[(r0 + 8) * HH + ncol], W[(r0 + 9) * HH + ncol]);
            }
        }
        const float* bias = isL2 ? b2 : b1;
        const float bs0 = bias[n0 + tg * 2];
        const float bs1 = bias[n0 + tg * 2 + 1];

        uint32_t pbase[8], pmbar[8];
#pragma unroll
        for (int r = 0; r < 8; ++r) {
            pbase[r] = mapa32(buf_a, (uint32_t)r);
            pmbar[r] = mapa32(mb_a,  (uint32_t)r);
        }

        int phA[2] = {0, 0}, phB[2] = {0, 0};
        const int r0s = grp * 16, r1s = (grp + 8) * 16;

        for (int u = 1; u <= TT; ++u) {
            const int b  = (u - 1) & 1;   // buffer holding h(u-1)
            const int pb = u & 1;         // outgoing buffer for h(u)

            float c0 = 0.f, c1 = 0.f, c2 = 0.f, c3 = 0.f;
            float e0 = 0.f, e1 = 0.f, e2 = 0.f, e3 = 0.f;

            if (u > 1) {
                const uint32_t* bufb = &s_buf[b][0][0][0];

                // ---- j=0: own slice (local STS last step, no wait) ----
                {
                    const uint32_t* blk = bufb + (int)rank * 256;
#pragma unroll
                    for (int half = 0; half < 2; ++half) {
                        int cA = (half * 8 + tg) ^ sw;
                        int cB = (half * 8 + 4 + tg) ^ sw;
                        uint32_t a0 = blk[r0s + cA], a1 = blk[r1s + cA];
                        uint32_t a2 = blk[r0s + cB], a3 = blk[r1s + cB];
                        if (half) mma16816(e0, e1, e2, e3, a0, a1, a2, a3, bfB[1][0], bfB[1][1]);
                        else      mma16816(c0, c1, c2, c3, a0, a1, a2, a3, bfB[0][0], bfB[0][1]);
                    }
                }
                // ---- wait group A (senders s=1..3), then j=1..3 ----
                mb_wait(mb_a + (uint32_t)((b * 2 + 0) * 8), (uint32_t)phA[b]);
                phA[b] ^= 1;
                if (tid == 0 && u + 2 <= TT)
                    mb_arrive_expect(mb_a + (uint32_t)((b * 2 + 0) * 8), 3072);
#pragma unroll
                for (int j = 1; j < 4; ++j) {
                    const uint32_t* blk = bufb + (((int)rank + 8 - j) & 7) * 256;
#pragma unroll
                    for (int half = 0; half < 2; ++half) {
                        int cA = (half * 8 + tg) ^ sw;
                        int cB = (half * 8 + 4 + tg) ^ sw;
                        uint32_t a0 = blk[r0s + cA], a1 = blk[r1s + cA];
                        uint32_t a2 = blk[r0s + cB], a3 = blk[r1s + cB];
                        if (half) mma16816(e0, e1, e2, e3, a0, a1, a2, a3, bfB[j*2+1][0], bfB[j*2+1][1]);
                        else      mma16816(c0, c1, c2, c3, a0, a1, a2, a3, bfB[j*2][0],   bfB[j*2][1]);
                    }
                }
                // ---- wait group B (senders s=4..7), then j=4..7 ----
                mb_wait(mb_a + (uint32_t)((b * 2 + 1) * 8), (uint32_t)phB[b]);
                phB[b] ^= 1;
                if (tid == 0 && u + 2 <= TT)
                    mb_arrive_expect(mb_a + (uint32_t)((b * 2 + 1) * 8), 4096);
#pragma unroll
                for (int j = 4; j < 8; ++j) {
                    const uint32_t* blk = bufb + (((int)rank + 8 - j) & 7) * 256;
#pragma unroll
                    for (int half = 0; half < 2; ++half) {
                        int cA = (half * 8 + tg) ^ sw;
                        int cB = (half * 8 + 4 + tg) ^ sw;
                        uint32_t a0 = blk[r0s + cA], a1 = blk[r1s + cA];
                        uint32_t a2 = blk[r0s + cB], a3 = blk[r1s + cB];
                        if (half) mma16816(e0, e1, e2, e3, a0, a1, a2, a3, bfB[j*2+1][0], bfB[j*2+1][1]);
                        else      mma16816(c0, c1, c2, c3, a0, a1, a2, a3, bfB[j*2][0],   bfB[j*2][1]);
                    }
                }
            }

            // ---- collect phase-A partials ----
            if (pb) BAR_SYNC_256(2); else BAR_SYNC_256(1);
            float2 pa01 = s_pA[pb][grp][w * 4 + tg];
            float2 pa23 = s_pA[pb][grp + 8][w * 4 + tg];
            if (pb) BAR_ARRIVE_256(4); else BAR_ARRIVE_256(3);

            float v0 = tanhf(c0 + e0 + pa01.x + bs0);
            float v1 = tanhf(c1 + e1 + pa01.y + bs1);
            float v2 = tanhf(c2 + e2 + pa23.x + bs0);
            float v3 = tanhf(c3 + e3 + pa23.y + bs1);
            uint32_t p01 = packh2(v0, v1);
            uint32_t p23 = packh2(v2, v3);

            // own slice direct into s_buf (doubles as bulk-copy source)
            const int cc = (w * 4 + tg) ^ sw;
            uint32_t* myblk = &s_buf[pb][rank][0][0];
            myblk[grp * 16 + cc]       = p01;
            myblk[(grp + 8) * 16 + cc] = p23;

            if (!isL2) {
                int r0g = bg * 16 + grp;
                *reinterpret_cast<uint32_t*>(&g_h1[u][r0g][n0 + tg * 2])     = p01;
                *reinterpret_cast<uint32_t*>(&g_h1[u][r0g + 8][n0 + tg * 2]) = p23;
            } else if (u == TT) {
                int r0g = bg * 16 + grp;
                *reinterpret_cast<uint32_t*>(&g_h2f[r0g][n0 + tg * 2])     = p01;
                *reinterpret_cast<uint32_t*>(&g_h2f[r0g + 8][n0 + tg * 2]) = p23;
            }
            BAR_SYNC_128(5);  // B-warps: STS complete before copies read s_buf

            // 7 staggered sends; s<=3 -> consumer's grpA barrier, else grpB
            if (u < TT && w == 0 && lane >= 1 && lane < 8) {
                asm volatile("fence.proxy.async.shared::cta;" ::: "memory");
                int c = ((int)rank + lane) & 7;
                uint32_t off = (uint32_t)(pb * 8192 + (int)rank * 1024);
                uint32_t rmb = pmbar[c] + (uint32_t)((pb * 2 + (lane > 3 ? 1 : 0)) * 8);
                bulk_s2s(pbase[c] + off, buf_a + off, 1024, rmb);
            }
            if (!isL2 && tid == 0)
                red_rel(&g_f1[u][bg][rank]);
        }
    } else {
        // ================= A-warps: non-recurrent producer =================
        const int atid  = tid - 128;
        const int alane = atid & 31;
        const int aw    = atid >> 5;
        const int grp   = alane >> 2;
        const int tg    = alane & 3;
        const int ncol  = (int)rank * 32 + aw * 8 + grp;
        const int NKTA  = isL2 ? 16 : 4;
        const int SA32  = isL2 ? 132 : 36;

        uint32_t bfA[16][2];
#pragma unroll
        for (int kt = 0; kt < 16; ++kt) {
            bfA[kt][0] = bfA[kt][1] = 0;
            if (kt < NKTA) {
                const float* W = isL2 ? Wx2 : Wx1;
                int r0 = kt * 16 + tg * 2;
                bfA[kt][0] = packh2(W[(r0 + 0) * HH + ncol], W[(r0 + 1) * HH + ncol]);
                bfA[kt][1] = packh2(W[(r0 + 8) * HH + ncol], W[(r0 + 9) * HH + ncol]);
            }
        }
        const int xrow = atid >> 3;
        const int xcb  = (atid & 7) * 8;

        for (int u = 1; u <= TT; ++u) {
            const int pb = u & 1;
            if (u > 2) { if (pb) BAR_SYNC_256(4); else BAR_SYNC_256(3); }

            if (!isL2) {
                const float* xp = x + ((size_t)(bg * 16 + xrow) * TT + (u - 1)) * DD + xcb;
                float4 xa = *reinterpret_cast<const float4*>(xp);
                float4 xb = *reinterpret_cast<const float4*>(xp + 4);
                BAR_SYNC_128(6);
                uint32_t* d = &s_stage[xrow * 36 + (xcb >> 1)];
                d[0] = packh2(xa.x, xa.y); d[1] = packh2(xa.z, xa.w);
                d[2] = packh2(xb.x, xb.y); d[3] = packh2(xb.z, xb.w);
                BAR_SYNC_128(6);
            } else {
                if (aw == 0 && alane < 8) {
                    const int* f = &g_f1[u][bg][alane];
                    uint32_t n = 0;
                    while (!ld_acq(f)) {
                        if (*(volatile int*)&g_abort) break;
                        if (++n > (1u << 24)) { *(volatile int*)&g_abort = 1; break; }
                    }
                }
                BAR_SYNC_128(6);
#pragma unroll
                for (int k = 0; k < 4; ++k) {
                    int idx = atid + k * 128;
                    int row = idx >> 5, c16 = idx & 31;
                    uint4 v = __ldcg(reinterpret_cast<const uint4*>(
                        &g_h1[u][bg * 16 + row][c16 * 8]));
                    *reinterpret_cast<uint4*>(&s_stage[row * 132 + c16 * 4]) = v;
                }
                BAR_SYNC_128(6);
            }

            float c0 = 0.f, c1 = 0.f, c2 = 0.f, c3 = 0.f;
            float e0 = 0.f, e1 = 0.f, e2 = 0.f, e3 = 0.f;
#pragma unroll
            for (int kt = 0; kt < 16; ++kt) {
                if (kt < NKTA) {
                    uint32_t a0 = s_stage[grp * SA32 + kt * 8 + tg];
                    uint32_t a1 = s_stage[(grp + 8) * SA32 + kt * 8 + tg];
                    uint32_t a2 = s_stage[grp * SA32 + kt * 8 + 4 + tg];
                    uint32_t a3 = s_stage[(grp + 8) * SA32 + kt * 8 + 4 + tg];
                    if (kt & 1) mma16816(e0, e1, e2, e3, a0, a1, a2, a3, bfA[kt][0], bfA[kt][1]);
                    else        mma16816(c0, c1, c2, c3, a0, a1, a2, a3, bfA[kt][0], bfA[kt][1]);
                }
            }
            s_pA[pb][grp][aw * 4 + tg]     = make_float2(c0 + e0, c1 + e1);
            s_pA[pb][grp + 8][aw * 4 + tg] = make_float2(c2 + e2, c3 + e3);
            if (pb) BAR_ARRIVE_256(2); else BAR_ARRIVE_256(1);
        }
    }

    asm volatile("barrier.cluster.arrive.aligned;" ::: "memory");
    asm volatile("barrier.cluster.wait.aligned;"   ::: "memory");
}

// ---------------- head: logits + softmax (fp32) -------------------------------
__global__ void k_head(const float* __restrict__ Wd, const float* __restrict__ bd,
                       float* __restrict__ out) {
    const int b = blockIdx.x;
    const int o = threadIdx.x;
    __shared__ float sh[HH];
    __shared__ float red[OO];

    for (int k = o; k < HH; k += OO)
        sh[k] = __half2float(g_h2f[b][k]);
    __syncthreads();

    float acc = bd[o];
#pragma unroll 8
    for (int k = 0; k < HH; ++k)
        acc = fmaf(sh[k], Wd[k * OO + o], acc);

    red[o] = acc;
    __syncthreads();
    for (int s = OO / 2; s > 0; s >>= 1) {
        if (o < s) red[o] = fmaxf(red[o], red[o + s]);
        __syncthreads();
    }
    float m = red[0];
    __syncthreads();
    float e = expf(acc - m);
    red[o] = e;
    __syncthreads();
    for (int s = OO / 2; s > 0; s >>= 1) {
        if (o < s) red[o] += red[o + s];
        __syncthreads();
    }
    out[b * OO + o] = e / red[0];
}

// ---------------- launch (k_rnn FIRST so ncu -s5 lands on it; statics are
// zero-initialized at load, k_init re-zeroes flags for the NEXT call) ----------
extern "C" void kernel_launch(void* const* d_in, const int* in_sizes, int n_in,
                              void* d_out, int out_size) {
    const float* x   = (const float*)d_in[0];
    const float* Wx1 = (const float*)d_in[1];
    const float* Wh1 = (const float*)d_in[2];
    const float* b1  = (const float*)d_in[3];
    const float* Wx2 = (const float*)d_in[4];
    const float* Wh2 = (const float*)d_in[5];
    const float* b2  = (const float*)d_in[6];
    const float* Wd  = (const float*)d_in[7];
    const float* bd  = (const float*)d_in[8];

    k_rnn<<<128, 256>>>(x, Wx1, Wh1, b1, Wx2, Wh2, b2);
    k_head<<<128, 128>>>(Wd, bd, (float*)d_out);
    k_init<<<64, 256>>>();
}

// round 11
// speedup vs baseline: 1.1230x; 1.1230x over previous
#include <cuda_runtime.h>
#include <cuda_fp16.h>
#include <stdint.h>

#define BB 128
#define TT 1024
#define DD 64
#define HH 256
#define OO 128

// ---------------- global state -------------------------------------------------
__device__ __half g_h1[(TT + 1)][BB][HH];   // full h1 history (L1 -> L2 handoff)
__device__ __half g_h2f[BB][HH];            // final h2(T) only
__device__ int    g_f1[(TT + 1)][8][8];     // per-producer flags for h1
__device__ int    g_abort;

__device__ __forceinline__ uint32_t packh2(float a, float b) {
    __half2 h = __floats2half2_rn(a, b);
    return *reinterpret_cast<uint32_t*>(&h);
}

__device__ __forceinline__ void mma16816(float& c0, float& c1, float& c2, float& c3,
                                         uint32_t a0, uint32_t a1, uint32_t a2, uint32_t a3,
                                         uint32_t b0, uint32_t b1) {
    asm volatile(
        "mma.sync.aligned.m16n8k16.row.col.f32.f16.f16.f32 "
        "{%0,%1,%2,%3}, {%4,%5,%6,%7}, {%8,%9}, {%0,%1,%2,%3};\n"
        : "+f"(c0), "+f"(c1), "+f"(c2), "+f"(c3)
        : "r"(a0), "r"(a1), "r"(a2), "r"(a3), "r"(b0), "r"(b1));
}

__device__ __forceinline__ uint32_t smem_u32(const void* p) {
    uint32_t a;
    asm("{ .reg .u64 t; cvta.to.shared.u64 t, %1; cvt.u32.u64 %0, t; }" : "=r"(a) : "l"(p));
    return a;
}

__device__ __forceinline__ uint32_t mapa32(uint32_t addr, uint32_t rank) {
    uint32_t r;
    asm("mapa.shared::cluster.u32 %0, %1, %2;" : "=r"(r) : "r"(addr), "r"(rank));
    return r;
}

__device__ __forceinline__ void bulk_s2s(uint32_t dst, uint32_t src, uint32_t bytes,
                                         uint32_t rmb) {
    asm volatile(
        "cp.async.bulk.shared::cluster.shared::cta.mbarrier::complete_tx::bytes "
        "[%0], [%1], %2, [%3];"
        :: "r"(dst), "r"(src), "r"(bytes), "r"(rmb) : "memory");
}

__device__ __forceinline__ void mb_init(uint32_t mb, uint32_t cnt) {
    asm volatile("mbarrier.init.shared.b64 [%0], %1;" :: "r"(mb), "r"(cnt) : "memory");
}

__device__ __forceinline__ void mb_arrive_expect(uint32_t mb, uint32_t bytes) {
    asm volatile("mbarrier.arrive.expect_tx.shared.b64 _, [%0], %1;"
                 :: "r"(mb), "r"(bytes) : "memory");
}

// cta-scope acquire: the ONLY behavioral change vs the 1403us kernel.
// (cluster-scope acquire suspected to lower to ~490cyc UCGABAR_WAIT.)
__device__ __forceinline__ void mb_wait(uint32_t mb, uint32_t ph) {
    uint32_t done = 0, n = 0;
    while (!done) {
        asm volatile(
            "{\n\t.reg .pred p;\n\t"
            "mbarrier.try_wait.parity.acquire.cta.shared::cta.b64 p, [%1], %2, 0x989680;\n\t"
            "selp.b32 %0, 1, 0, p;\n\t}"
            : "=r"(done) : "r"(mb), "r"(ph) : "memory");
        if (!done) {
            if (*(volatile int*)&g_abort) break;
            if (++n > (1u << 22)) { *(volatile int*)&g_abort = 1; break; }
        }
    }
}

__device__ __forceinline__ int ld_acq(const int* p) {
    int v;
    asm volatile("ld.acquire.gpu.global.s32 %0, [%1];" : "=r"(v) : "l"(p) : "memory");
    return v;
}

__device__ __forceinline__ void red_rel(int* p) {
    asm volatile("red.release.gpu.global.add.s32 [%0], %1;" :: "l"(p), "r"(1) : "memory");
}

#define BAR_ARRIVE_256(id) asm volatile("bar.arrive " #id ", 256;" ::: "memory")
#define BAR_SYNC_256(id)   asm volatile("bar.sync "   #id ", 256;" ::: "memory")
#define BAR_SYNC_128(id)   asm volatile("bar.sync "   #id ", 128;" ::: "memory")

// ---------------- init (runs LAST: prepares flags for the NEXT launch) ---------
__global__ void k_init() {
    int* p = &g_f1[0][0][0];
    const int n = (TT + 1) * 8 * 8;
    for (int i = blockIdx.x * blockDim.x + threadIdx.x; i < n;
         i += gridDim.x * blockDim.x)
        p[i] = 0;
    if (blockIdx.x == 0 && threadIdx.x == 0) g_abort = 0;
}

// ---------------- persistent RNN: 16 clusters of 8 CTAs, 256 thr/CTA -----------
// warps 0-3: recurrence (phase B + epilogue + broadcast)
// warps 4-7: non-recurrent producer (x/h1 staging + phase A MMA + bias -> partials)
__global__ void __launch_bounds__(256, 1) __cluster_dims__(8, 1, 1)
k_rnn(const float* __restrict__ x,
      const float* __restrict__ Wx1, const float* __restrict__ Wh1,
      const float* __restrict__ b1,
      const float* __restrict__ Wx2, const float* __restrict__ Wh2,
      const float* __restrict__ b2) {
    const int tid  = threadIdx.x;
    const int lane = tid & 31;
    const int w    = tid >> 5;         // 0..7

    uint32_t rank;
    asm("mov.u32 %0, %%cluster_ctarank;" : "=r"(rank));

    const int  cl   = blockIdx.x >> 3;
    const bool isL2 = (cl >= 8);
    const int  bg   = isL2 ? cl - 8 : cl;

    // shared memory
    __shared__ __align__(16) uint32_t s_buf[2][8][16][16];   // 16 KB  h exchange
    __shared__ __align__(16) uint32_t s_out[2][16][16];      //  2 KB  outgoing h
    __shared__ __align__(16) uint32_t s_stage[16 * 132];     //  8.25 KB x/h1 operand
    __shared__ __align__(16) float2   s_pA[2][16][18];       //  4.5 KB fp32 partials
    __shared__ __align__(8)  uint64_t s_mb[2];

    const uint32_t buf_a = smem_u32(&s_buf[0][0][0][0]);
    const uint32_t out_a = smem_u32(&s_out[0][0][0]);
    const uint32_t mb_a  = smem_u32(&s_mb[0]);

    // zero h buffers (h(0)=0), init barriers
    for (int i = tid; i < 2 * 8 * 16 * 16; i += 256) (&s_buf[0][0][0][0])[i] = 0;
    if (tid == 0) {
        mb_init(mb_a, 1);
        mb_init(mb_a + 8, 1);
        asm volatile("fence.mbarrier_init.release.cluster;" ::: "memory");
    }
    __syncthreads();
    asm volatile("barrier.cluster.arrive.aligned;" ::: "memory");
    asm volatile("barrier.cluster.wait.aligned;"   ::: "memory");
    if (tid == 0) {  // pre-arm: first use t=2 -> mb1(b=1), t=3 -> mb0(b=0)
        mb_arrive_expect(mb_a + 8, 8192);
        mb_arrive_expect(mb_a, 8192);
    }

    if (w < 4) {
        // ================= B-warps: recurrence =================
        const int grp = lane >> 2;     // 0..7
        const int tg  = lane & 3;      // 0..3
        const int n0  = (int)rank * 32 + w * 8;
        const int ncol = n0 + grp;
        const int sw  = (grp & 6) * 2;

        uint32_t bfB[16][2];
#pragma unroll
        for (int kt = 0; kt < 16; ++kt) {
            const float* W = isL2 ? Wh2 : Wh1;
            int r0 = kt * 16 + tg * 2;
            bfB[kt][0] = packh2(W[(r0 + 0) * HH + ncol], W[(r0 + 1) * HH + ncol]);
            bfB[kt][1] = packh2(W[(r0 + 8) * HH + ncol], W[(r0 + 9) * HH + ncol]);
        }

        uint32_t pbase[8], pmbar[8];
#pragma unroll
        for (int r = 0; r < 8; ++r) {
            pbase[r] = mapa32(buf_a, (uint32_t)r);
            pmbar[r] = mapa32(mb_a,  (uint32_t)r);
        }

        int ph0 = 0, ph1 = 0;
        const int r0s = grp * 16, r1s = (grp + 8) * 16;

        for (int u = 1; u <= TT; ++u) {
            const int b  = (u - 1) & 1;
            const int pb = u & 1;

            if (u > 1) {
                if (b) { mb_wait(mb_a + 8, (uint32_t)ph1); ph1 ^= 1; }
                else   { mb_wait(mb_a,     (uint32_t)ph0); ph0 ^= 1; }
                if (tid == 0 && u < TT)
                    mb_arrive_expect(mb_a + (b ? 8 : 0), 8192);
            }

            // phase B MMA: h(u-1) * Wh, dual accumulator chains
            float c0 = 0.f, c1 = 0.f, c2 = 0.f, c3 = 0.f;
            float e0 = 0.f, e1 = 0.f, e2 = 0.f, e3 = 0.f;
            {
                const uint32_t* bufb = &s_buf[b][0][0][0];
#pragma unroll
                for (int kt = 0; kt < 16; ++kt) {
                    const uint32_t* blk = bufb + (kt >> 1) * 256;
                    int cA = ((kt & 1) * 8 + tg) ^ sw;
                    int cB = ((kt & 1) * 8 + 4 + tg) ^ sw;
                    uint32_t a0 = blk[r0s + cA];
                    uint32_t a1 = blk[r1s + cA];
                    uint32_t a2 = blk[r0s + cB];
                    uint32_t a3 = blk[r1s + cB];
                    if (kt & 1) mma16816(e0, e1, e2, e3, a0, a1, a2, a3, bfB[kt][0], bfB[kt][1]);
                    else        mma16816(c0, c1, c2, c3, a0, a1, a2, a3, bfB[kt][0], bfB[kt][1]);
                }
            }

            // collect phase-A partials (bias already folded in by A-warps)
            if (pb) BAR_SYNC_256(2); else BAR_SYNC_256(1);
            float2 pa01 = s_pA[pb][grp][w * 4 + tg];
            float2 pa23 = s_pA[pb][grp + 8][w * 4 + tg];
            if (pb) BAR_ARRIVE_256(4); else BAR_ARRIVE_256(3);

            float v0 = tanhf(c0 + e0 + pa01.x);
            float v1 = tanhf(c1 + e1 + pa01.y);
            float v2 = tanhf(c2 + e2 + pa23.x);
            float v3 = tanhf(c3 + e3 + pa23.y);
            uint32_t p01 = packh2(v0, v1);
            uint32_t p23 = packh2(v2, v3);

            const int cc = (w * 4 + tg) ^ sw;
            s_out[pb][grp][cc]     = p01;
            s_out[pb][grp + 8][cc] = p23;

            if (!isL2) {
                int r0g = bg * 16 + grp;
                *reinterpret_cast<uint32_t*>(&g_h1[u][r0g][n0 + tg * 2])     = p01;
                *reinterpret_cast<uint32_t*>(&g_h1[u][r0g + 8][n0 + tg * 2]) = p23;
            } else if (u == TT) {
                int r0g = bg * 16 + grp;
                *reinterpret_cast<uint32_t*>(&g_h2f[r0g][n0 + tg * 2])     = p01;
                *reinterpret_cast<uint32_t*>(&g_h2f[r0g + 8][n0 + tg * 2]) = p23;
            }
            BAR_SYNC_128(5);  // B-warps only: s_out complete, STGs done

            if (u < TT && w == 0 && lane < 8) {
                asm volatile("fence.proxy.async.shared::cta;" ::: "memory");
                uint32_t dst = pbase[lane] + (uint32_t)(pb * 8192 + (int)rank * 1024);
                uint32_t src = out_a + (uint32_t)(pb * 1024);
                uint32_t rmb = pmbar[lane] + (uint32_t)(pb * 8);
                bulk_s2s(dst, src, 1024, rmb);
            }
            if (!isL2 && tid == 0)
                red_rel(&g_f1[u][bg][rank]);
        }
    } else {
        // ================= A-warps: non-recurrent producer =================
        const int atid  = tid - 128;
        const int alane = atid & 31;
        const int aw    = atid >> 5;
        const int grp   = alane >> 2;
        const int tg    = alane & 3;
        const int an0   = (int)rank * 32 + aw * 8;
        const int ncol  = an0 + grp;
        const int NKTA  = isL2 ? 16 : 4;
        const int SA32  = isL2 ? 132 : 36;

        uint32_t bfA[16][2];
#pragma unroll
        for (int kt = 0; kt < 16; ++kt) {
            bfA[kt][0] = bfA[kt][1] = 0;
            if (kt < NKTA) {
                const float* W = isL2 ? Wx2 : Wx1;
                int r0 = kt * 16 + tg * 2;
                bfA[kt][0] = packh2(W[(r0 + 0) * HH + ncol], W[(r0 + 1) * HH + ncol]);
                bfA[kt][1] = packh2(W[(r0 + 8) * HH + ncol], W[(r0 + 9) * HH + ncol]);
            }
        }
        const float* bias = isL2 ? b2 : b1;
        const float bs0 = bias[an0 + tg * 2];
        const float bs1 = bias[an0 + tg * 2 + 1];

        const int xrow = atid >> 3;
        const int xcb  = (atid & 7) * 8;

        for (int u = 1; u <= TT; ++u) {
            const int pb = u & 1;
            if (u > 2) { if (pb) BAR_SYNC_256(4); else BAR_SYNC_256(3); }

            if (!isL2) {
                const float* xp = x + ((size_t)(bg * 16 + xrow) * TT + (u - 1)) * DD + xcb;
                float4 xa = *reinterpret_cast<const float4*>(xp);
                float4 xb = *reinterpret_cast<const float4*>(xp + 4);
                BAR_SYNC_128(6);
                uint32_t* d = &s_stage[xrow * 36 + (xcb >> 1)];
                d[0] = packh2(xa.x, xa.y); d[1] = packh2(xa.z, xa.w);
                d[2] = packh2(xb.x, xb.y); d[3] = packh2(xb.z, xb.w);
                BAR_SYNC_128(6);
            } else {
                if (aw == 0 && alane < 8) {
                    const int* f = &g_f1[u][bg][alane];
                    uint32_t n = 0;
                    while (!ld_acq(f)) {
                        if (*(volatile int*)&g_abort) break;
                        if (++n > (1u << 24)) { *(volatile int*)&g_abort = 1; break; }
                    }
                }
                BAR_SYNC_128(6);
#pragma unroll
                for (int k = 0; k < 4; ++k) {
                    int idx = atid + k * 128;
                    int row = idx >> 5, c16 = idx & 31;
                    uint4 v = __ldcg(reinterpret_cast<const uint4*>(
                        &g_h1[u][bg * 16 + row][c16 * 8]));
                    *reinterpret_cast<uint4*>(&s_stage[row * 132 + c16 * 4]) = v;
                }
                BAR_SYNC_128(6);
            }

            float c0 = 0.f, c1 = 0.f, c2 = 0.f, c3 = 0.f;
            float e0 = 0.f, e1 = 0.f, e2 = 0.f, e3 = 0.f;
#pragma unroll
            for (int kt = 0; kt < 16; ++kt) {
                if (kt < NKTA) {
                    uint32_t a0 = s_stage[grp * SA32 + kt * 8 + tg];
                    uint32_t a1 = s_stage[(grp + 8) * SA32 + kt * 8 + tg];
                    uint32_t a2 = s_stage[grp * SA32 + kt * 8 + 4 + tg];
                    uint32_t a3 = s_stage[(grp + 8) * SA32 + kt * 8 + 4 + tg];
                    if (kt & 1) mma16816(e0, e1, e2, e3, a0, a1, a2, a3, bfA[kt][0], bfA[kt][1]);
                    else        mma16816(c0, c1, c2, c3, a0, a1, a2, a3, bfA[kt][0], bfA[kt][1]);
                }
            }
            // bias folded here (off the recurrence critical path)
            s_pA[pb][grp][aw * 4 + tg]     = make_float2(c0 + e0 + bs0, c1 + e1 + bs1);
            s_pA[pb][grp + 8][aw * 4 + tg] = make_float2(c2 + e2 + bs0, c3 + e3 + bs1);
            if (pb) BAR_ARRIVE_256(2); else BAR_ARRIVE_256(1);
        }
    }

    asm volatile("barrier.cluster.arrive.aligned;" ::: "memory");
    asm volatile("barrier.cluster.wait.aligned;"   ::: "memory");
}

// ---------------- head: logits + softmax (fp32) -------------------------------
__global__ void k_head(const float* __restrict__ Wd, const float* __restrict__ bd,
                       float* __restrict__ out) {
    const int b = blockIdx.x;
    const int o = threadIdx.x;
    __shared__ float sh[HH];
    __shared__ float red[OO];

    for (int k = o; k < HH; k += OO)
        sh[k] = __half2float(g_h2f[b][k]);
    __syncthreads();

    float acc = bd[o];
#pragma unroll 8
    for (int k = 0; k < HH; ++k)
        acc = fmaf(sh[k], Wd[k * OO + o], acc);

    red[o] = acc;
    __syncthreads();
    for (int s = OO / 2; s > 0; s >>= 1) {
        if (o < s) red[o] = fmaxf(red[o], red[o + s]);
        __syncthreads();
    }
    float m = red[0];
    __syncthreads();
    float e = expf(acc - m);
    red[o] = e;
    __syncthreads();
    for (int s = OO / 2; s > 0; s >>= 1) {
        if (o < s) red[o] += red[o + s];
        __syncthreads();
    }
    out[b * OO + o] = e / red[0];
}

// ---------------- launch (k_rnn first; statics zero-initialized at load,
// k_init re-zeroes flags for the NEXT call) ------------------------------------
extern "C" void kernel_launch(void* const* d_in, const int* in_sizes, int n_in,
                              void* d_out, int out_size) {
    const float* x   = (const float*)d_in[0];
    const float* Wx1 = (const float*)d_in[1];
    const float* Wh1 = (const float*)d_in[2];
    const float* b1  = (const float*)d_in[3];
    const float* Wx2 = (const float*)d_in[4];
    const float* Wh2 = (const float*)d_in[5];
    const float* b2  = (const float*)d_in[6];
    const float* Wd  = (const float*)d_in[7];
    const float* bd  = (const float*)d_in[8];

    k_rnn<<<128, 256>>>(x, Wx1, Wh1, b1, Wx2, Wh2, b2);
    k_head<<<128, 128>>>(Wd, bd, (float*)d_out);
    k_init<<<64, 256>>>();
}

// round 12
// speedup vs baseline: 1.6823x; 1.4980x over previous
#include <cuda_runtime.h>
#include <cuda_fp16.h>
#include <stdint.h>

#define BB 128
#define TT 1024
#define DD 64
#define HH 256
#define OO 128

// ---------------- global state -------------------------------------------------
__device__ __half g_h1[(TT + 1)][BB][HH];   // full h1 history (L1 -> L2 handoff)
__device__ __half g_h2f[BB][HH];            // final h2(T) only
__device__ int    g_f1[(TT + 1)][8][8];     // per-producer flags for h1
__device__ int    g_abort;

__device__ __forceinline__ uint32_t packh2(float a, float b) {
    __half2 h = __floats2half2_rn(a, b);
    return *reinterpret_cast<uint32_t*>(&h);
}

// fast tanh: 1 - 2/(exp(2x)+1); saturates correctly (+inf -> 1, 0 -> -1)
__device__ __forceinline__ float ftanh(float x) {
    float e = __expf(2.0f * x);
    return 1.0f - __fdividef(2.0f, e + 1.0f);
}

__device__ __forceinline__ void mma16816(float& c0, float& c1, float& c2, float& c3,
                                         uint32_t a0, uint32_t a1, uint32_t a2, uint32_t a3,
                                         uint32_t b0, uint32_t b1) {
    asm volatile(
        "mma.sync.aligned.m16n8k16.row.col.f32.f16.f16.f32 "
        "{%0,%1,%2,%3}, {%4,%5,%6,%7}, {%8,%9}, {%0,%1,%2,%3};\n"
        : "+f"(c0), "+f"(c1), "+f"(c2), "+f"(c3)
        : "r"(a0), "r"(a1), "r"(a2), "r"(a3), "r"(b0), "r"(b1));
}

__device__ __forceinline__ uint32_t smem_u32(const void* p) {
    uint32_t a;
    asm("{ .reg .u64 t; cvta.to.shared.u64 t, %1; cvt.u32.u64 %0, t; }" : "=r"(a) : "l"(p));
    return a;
}

__device__ __forceinline__ uint32_t mapa32(uint32_t addr, uint32_t rank) {
    uint32_t r;
    asm("mapa.shared::cluster.u32 %0, %1, %2;" : "=r"(r) : "r"(addr), "r"(rank));
    return r;
}

__device__ __forceinline__ void bulk_s2s(uint32_t dst, uint32_t src, uint32_t bytes,
                                         uint32_t rmb) {
    asm volatile(
        "cp.async.bulk.shared::cluster.shared::cta.mbarrier::complete_tx::bytes "
        "[%0], [%1], %2, [%3];"
        :: "r"(dst), "r"(src), "r"(bytes), "r"(rmb) : "memory");
}

__device__ __forceinline__ void mb_init(uint32_t mb, uint32_t cnt) {
    asm volatile("mbarrier.init.shared.b64 [%0], %1;" :: "r"(mb), "r"(cnt) : "memory");
}

__device__ __forceinline__ void mb_arrive_expect(uint32_t mb, uint32_t bytes) {
    asm volatile("mbarrier.arrive.expect_tx.shared.b64 _, [%0], %1;"
                 :: "r"(mb), "r"(bytes) : "memory");
}

// cluster-scope acquire — EXACT R7 form (the 1403us configuration)
__device__ __forceinline__ void mb_wait(uint32_t mb, uint32_t ph) {
    uint32_t done = 0, n = 0;
    while (!done) {
        asm volatile(
            "{\n\t.reg .pred p;\n\t"
            "mbarrier.try_wait.parity.acquire.cluster.shared::cta.b64 p, [%1], %2, 0x989680;\n\t"
            "selp.b32 %0, 1, 0, p;\n\t}"
            : "=r"(done) : "r"(mb), "r"(ph) : "memory");
        if (!done) {
            if (*(volatile int*)&g_abort) break;
            if (++n > (1u << 22)) { *(volatile int*)&g_abort = 1; break; }
        }
    }
}

__device__ __forceinline__ int ld_acq(const int* p) {
    int v;
    asm volatile("ld.acquire.gpu.global.s32 %0, [%1];" : "=r"(v) : "l"(p) : "memory");
    return v;
}

__device__ __forceinline__ void red_rel(int* p) {
    asm volatile("red.release.gpu.global.add.s32 [%0], %1;" :: "l"(p), "r"(1) : "memory");
}

#define BAR_ARRIVE_256(id) asm volatile("bar.arrive " #id ", 256;" ::: "memory")
#define BAR_SYNC_256(id)   asm volatile("bar.sync "   #id ", 256;" ::: "memory")
#define BAR_SYNC_128(id)   asm volatile("bar.sync "   #id ", 128;" ::: "memory")

// ---------------- init ---------------------------------------------------------
__global__ void k_init() {
    int* p = &g_f1[0][0][0];
    const int n = (TT + 1) * 8 * 8;
    for (int i = blockIdx.x * blockDim.x + threadIdx.x; i < n;
         i += gridDim.x * blockDim.x)
        p[i] = 0;
    if (blockIdx.x == 0 && threadIdx.x == 0) g_abort = 0;
}

// ---------------- persistent RNN: 16 clusters of 8 CTAs, 256 thr/CTA -----------
// warps 0-3: recurrence (phase B + epilogue + broadcast)
// warps 4-7: non-recurrent producer (x/h1 staging + phase A MMA + bias -> partials)
__global__ void __launch_bounds__(256, 1) __cluster_dims__(8, 1, 1)
k_rnn(const float* __restrict__ x,
      const float* __restrict__ Wx1, const float* __restrict__ Wh1,
      const float* __restrict__ b1,
      const float* __restrict__ Wx2, const float* __restrict__ Wh2,
      const float* __restrict__ b2) {
    const int tid  = threadIdx.x;
    const int lane = tid & 31;
    const int w    = tid >> 5;         // 0..7

    uint32_t rank;
    asm("mov.u32 %0, %%cluster_ctarank;" : "=r"(rank));

    const int  cl   = blockIdx.x >> 3;
    const bool isL2 = (cl >= 8);
    const int  bg   = isL2 ? cl - 8 : cl;

    // shared memory
    __shared__ __align__(16) uint32_t s_buf[2][8][16][16];   // 16 KB  h exchange
    __shared__ __align__(16) uint32_t s_out[2][16][16];      //  2 KB  outgoing h
    __shared__ __align__(16) uint32_t s_stage[16 * 132];     //  8.25 KB x/h1 operand
    __shared__ __align__(16) float2   s_pA[2][16][18];       //  4.5 KB fp32 partials
    __shared__ __align__(8)  uint64_t s_mb[2];

    const uint32_t buf_a = smem_u32(&s_buf[0][0][0][0]);
    const uint32_t out_a = smem_u32(&s_out[0][0][0]);
    const uint32_t mb_a  = smem_u32(&s_mb[0]);

    // zero h buffers (h(0)=0), init barriers
    for (int i = tid; i < 2 * 8 * 16 * 16; i += 256) (&s_buf[0][0][0][0])[i] = 0;
    if (tid == 0) {
        mb_init(mb_a, 1);
        mb_init(mb_a + 8, 1);
        asm volatile("fence.mbarrier_init.release.cluster;" ::: "memory");
    }
    __syncthreads();
    asm volatile("barrier.cluster.arrive.aligned;" ::: "memory");
    asm volatile("barrier.cluster.wait.aligned;"   ::: "memory");
    if (tid == 0) {  // pre-arm: first use t=2 -> mb1(b=1), t=3 -> mb0(b=0)
        mb_arrive_expect(mb_a + 8, 8192);
        mb_arrive_expect(mb_a, 8192);
    }

    if (w < 4) {
        // ================= B-warps: recurrence =================
        const int grp = lane >> 2;     // 0..7
        const int tg  = lane & 3;      // 0..3
        const int n0  = (int)rank * 32 + w * 8;
        const int ncol = n0 + grp;
        const int sw  = (grp & 6) * 2;

        uint32_t bfB[16][2];
#pragma unroll
        for (int kt = 0; kt < 16; ++kt) {
            const float* W = isL2 ? Wh2 : Wh1;
            int r0 = kt * 16 + tg * 2;
            bfB[kt][0] = packh2(W[(r0 + 0) * HH + ncol], W[(r0 + 1) * HH + ncol]);
            bfB[kt][1] = packh2(W[(r0 + 8) * HH + ncol], W[(r0 + 9) * HH + ncol]);
        }

        uint32_t pbase[8], pmbar[8];
#pragma unroll
        for (int r = 0; r < 8; ++r) {
            pbase[r] = mapa32(buf_a, (uint32_t)r);
            pmbar[r] = mapa32(mb_a,  (uint32_t)r);
        }

        int ph0 = 0, ph1 = 0;
        const int r0s = grp * 16, r1s = (grp + 8) * 16;

        for (int u = 1; u <= TT; ++u) {
            const int b  = (u - 1) & 1;
            const int pb = u & 1;

            if (u > 1) {
                if (b) { mb_wait(mb_a + 8, (uint32_t)ph1); ph1 ^= 1; }
                else   { mb_wait(mb_a,     (uint32_t)ph0); ph0 ^= 1; }
                if (tid == 0 && u < TT)
                    mb_arrive_expect(mb_a + (b ? 8 : 0), 8192);
            }

            // phase B MMA: h(u-1) * Wh, dual accumulator chains
            float c0 = 0.f, c1 = 0.f, c2 = 0.f, c3 = 0.f;
            float e0 = 0.f, e1 = 0.f, e2 = 0.f, e3 = 0.f;
            {
                const uint32_t* bufb = &s_buf[b][0][0][0];
#pragma unroll
                for (int kt = 0; kt < 16; ++kt) {
                    const uint32_t* blk = bufb + (kt >> 1) * 256;
                    int cA = ((kt & 1) * 8 + tg) ^ sw;
                    int cB = ((kt & 1) * 8 + 4 + tg) ^ sw;
                    uint32_t a0 = blk[r0s + cA];
                    uint32_t a1 = blk[r1s + cA];
                    uint32_t a2 = blk[r0s + cB];
                    uint32_t a3 = blk[r1s + cB];
                    if (kt & 1) mma16816(e0, e1, e2, e3, a0, a1, a2, a3, bfB[kt][0], bfB[kt][1]);
                    else        mma16816(c0, c1, c2, c3, a0, a1, a2, a3, bfB[kt][0], bfB[kt][1]);
                }
            }

            // collect phase-A partials (bias already folded in by A-warps)
            if (pb) BAR_SYNC_256(2); else BAR_SYNC_256(1);
            float2 pa01 = s_pA[pb][grp][w * 4 + tg];
            float2 pa23 = s_pA[pb][grp + 8][w * 4 + tg];
            if (pb) BAR_ARRIVE_256(4); else BAR_ARRIVE_256(3);

            float v0 = ftanh(c0 + e0 + pa01.x);
            float v1 = ftanh(c1 + e1 + pa01.y);
            float v2 = ftanh(c2 + e2 + pa23.x);
            float v3 = ftanh(c3 + e3 + pa23.y);
            uint32_t p01 = packh2(v0, v1);
            uint32_t p23 = packh2(v2, v3);

            const int cc = (w * 4 + tg) ^ sw;
            s_out[pb][grp][cc]     = p01;
            s_out[pb][grp + 8][cc] = p23;

            if (!isL2) {
                int r0g = bg * 16 + grp;
                *reinterpret_cast<uint32_t*>(&g_h1[u][r0g][n0 + tg * 2])     = p01;
                *reinterpret_cast<uint32_t*>(&g_h1[u][r0g + 8][n0 + tg * 2]) = p23;
            } else if (u == TT) {
                int r0g = bg * 16 + grp;
                *reinterpret_cast<uint32_t*>(&g_h2f[r0g][n0 + tg * 2])     = p01;
                *reinterpret_cast<uint32_t*>(&g_h2f[r0g + 8][n0 + tg * 2]) = p23;
            }
            BAR_SYNC_128(5);  // B-warps only: s_out complete, STGs done

            if (u < TT && w == 0 && lane < 8) {
                asm volatile("fence.proxy.async.shared::cta;" ::: "memory");
                uint32_t dst = pbase[lane] + (uint32_t)(pb * 8192 + (int)rank * 1024);
                uint32_t src = out_a + (uint32_t)(pb * 1024);
                uint32_t rmb = pmbar[lane] + (uint32_t)(pb * 8);
                bulk_s2s(dst, src, 1024, rmb);
            }
            if (!isL2 && tid == 0)
                red_rel(&g_f1[u][bg][rank]);
        }
    } else {
        // ================= A-warps: non-recurrent producer =================
        const int atid  = tid - 128;
        const int alane = atid & 31;
        const int aw    = atid >> 5;
        const int grp   = alane >> 2;
        const int tg    = alane & 3;
        const int an0   = (int)rank * 32 + aw * 8;
        const int ncol  = an0 + grp;
        const int NKTA  = isL2 ? 16 : 4;
        const int SA32  = isL2 ? 132 : 36;

        uint32_t bfA[16][2];
#pragma unroll
        for (int kt = 0; kt < 16; ++kt) {
            bfA[kt][0] = bfA[kt][1] = 0;
            if (kt < NKTA) {
                const float* W = isL2 ? Wx2 : Wx1;
                int r0 = kt * 16 + tg * 2;
                bfA[kt][0] = packh2(W[(r0 + 0) * HH + ncol], W[(r0 + 1) * HH + ncol]);
                bfA[kt][1] = packh2(W[(r0 + 8) * HH + ncol], W[(r0 + 9) * HH + ncol]);
            }
        }
        const float* bias = isL2 ? b2 : b1;
        const float bs0 = bias[an0 + tg * 2];
        const float bs1 = bias[an0 + tg * 2 + 1];

        const int xrow = atid >> 3;
        const int xcb  = (atid & 7) * 8;

        for (int u = 1; u <= TT; ++u) {
            const int pb = u & 1;
            if (u > 2) { if (pb) BAR_SYNC_256(4); else BAR_SYNC_256(3); }

            if (!isL2) {
                const float* xp = x + ((size_t)(bg * 16 + xrow) * TT + (u - 1)) * DD + xcb;
                float4 xa = *reinterpret_cast<const float4*>(xp);
                float4 xb = *reinterpret_cast<const float4*>(xp + 4);
                BAR_SYNC_128(6);
                uint32_t* d = &s_stage[xrow * 36 + (xcb >> 1)];
                d[0] = packh2(xa.x, xa.y); d[1] = packh2(xa.z, xa.w);
                d[2] = packh2(xb.x, xb.y); d[3] = packh2(xb.z, xb.w);
                BAR_SYNC_128(6);
            } else {
                if (aw == 0 && alane < 8) {
                    const int* f = &g_f1[u][bg][alane];
                    uint32_t n = 0;
                    while (!ld_acq(f)) {
                        if (*(volatile int*)&g_abort) break;
                        if (++n > (1u << 24)) { *(volatile int*)&g_abort = 1; break; }
                    }
                }
                BAR_SYNC_128(6);
#pragma unroll
                for (int k = 0; k < 4; ++k) {
                    int idx = atid + k * 128;
                    int row = idx >> 5, c16 = idx & 31;
                    uint4 v = __ldcg(reinterpret_cast<const uint4*>(
                        &g_h1[u][bg * 16 + row][c16 * 8]));
                    *reinterpret_cast<uint4*>(&s_stage[row * 132 + c16 * 4]) = v;
                }
                BAR_SYNC_128(6);
            }

            float c0 = 0.f, c1 = 0.f, c2 = 0.f, c3 = 0.f;
            float e0 = 0.f, e1 = 0.f, e2 = 0.f, e3 = 0.f;
#pragma unroll
            for (int kt = 0; kt < 16; ++kt) {
                if (kt < NKTA) {
                    uint32_t a0 = s_stage[grp * SA32 + kt * 8 + tg];
                    uint32_t a1 = s_stage[(grp + 8) * SA32 + kt * 8 + tg];
                    uint32_t a2 = s_stage[grp * SA32 + kt * 8 + 4 + tg];
                    uint32_t a3 = s_stage[(grp + 8) * SA32 + kt * 8 + 4 + tg];
                    if (kt & 1) mma16816(e0, e1, e2, e3, a0, a1, a2, a3, bfA[kt][0], bfA[kt][1]);
                    else        mma16816(c0, c1, c2, c3, a0, a1, a2, a3, bfA[kt][0], bfA[kt][1]);
                }
            }
            // bias folded here (off the recurrence critical path)
            s_pA[pb][grp][aw * 4 + tg]     = make_float2(c0 + e0 + bs0, c1 + e1 + bs1);
            s_pA[pb][grp + 8][aw * 4 + tg] = make_float2(c2 + e2 + bs0, c3 + e3 + bs1);
            if (pb) BAR_ARRIVE_256(2); else BAR_ARRIVE_256(1);
        }
    }

    asm volatile("barrier.cluster.arrive.aligned;" ::: "memory");
    asm volatile("barrier.cluster.wait.aligned;"   ::: "memory");
}

// ---------------- head: logits + softmax (fp32) -------------------------------
__global__ void k_head(const float* __restrict__ Wd, const float* __restrict__ bd,
                       float* __restrict__ out) {
    const int b = blockIdx.x;
    const int o = threadIdx.x;
    __shared__ float sh[HH];
    __shared__ float red[OO];

    for (int k = o; k < HH; k += OO)
        sh[k] = __half2float(g_h2f[b][k]);
    __syncthreads();

    float acc = bd[o];
#pragma unroll 8
    for (int k = 0; k < HH; ++k)
        acc = fmaf(sh[k], Wd[k * OO + o], acc);

    red[o] = acc;
    __syncthreads();
    for (int s = OO / 2; s > 0; s >>= 1) {
        if (o < s) red[o] = fmaxf(red[o], red[o + s]);
        __syncthreads();
    }
    float m = red[0];
    __syncthreads();
    float e = expf(acc - m);
    red[o] = e;
    __syncthreads();
    for (int s = OO / 2; s > 0; s >>= 1) {
        if (o < s) red[o] += red[o + s];
        __syncthreads();
    }
    out[b * OO + o] = e / red[0];
}

// ---------------- launch (EXACT R7 order: k_init, k_rnn, k_head) ---------------
extern "C" void kernel_launch(void* const* d_in, const int* in_sizes, int n_in,
                              void* d_out, int out_size) {
    const float* x   = (const float*)d_in[0];
    const float* Wx1 = (const float*)d_in[1];
    const float* Wh1 = (const float*)d_in[2];
    const float* b1  = (const float*)d_in[3];
    const float* Wx2 = (const float*)d_in[4];
    const float* Wh2 = (const float*)d_in[5];
    const float* b2  = (const float*)d_in[6];
    const float* Wd  = (const float*)d_in[7];
    const float* bd  = (const float*)d_in[8];

    k_init<<<64, 256>>>();
    k_rnn<<<128, 256>>>(x, Wx1, Wh1, b1, Wx2, Wh2, b2);
    k_head<<<128, 128>>>(Wd, bd, (float*)d_out);
}